// round 1
// baseline (speedup 1.0000x reference)
#include <cuda_runtime.h>
#include <math.h>

// NT-Xent loss, fused. N = 2B = 8192 rows, D = 256.
// reps[2k] = zjs[k], reps[2k+1] = zis[k]; target[i] = i^1.
// Scores bounded in [-2,2] (cosine/0.5) -> fixed-shift logsumexp, no max pass.

#define NROWS 8192
#define DIM   256
#define BM    64
#define BN    128
#define KC    64
#define NTILES  (NROWS / BN)   // 64
#define NBLOCKS (NROWS / BM)   // 128

// scratch (no cudaMalloc allowed)
__device__ __align__(16) float g_zn[NROWS * DIM];   // normalized, interleaved rows (8 MB)
__device__ float g_partial[NBLOCKS];                // per-block loss sums

// ---------------------------------------------------------------------------
// Kernel 1: interleave + L2-normalize rows.  grid = NROWS blocks x DIM threads.
// ---------------------------------------------------------------------------
__global__ void normalize_kernel(const float* __restrict__ zis,
                                 const float* __restrict__ zjs) {
    int r = blockIdx.x;
    int t = threadIdx.x;
    const float* src = (r & 1) ? (zis + (size_t)(r >> 1) * DIM)
                               : (zjs + (size_t)(r >> 1) * DIM);
    float v = src[t];
    __shared__ float red[DIM];
    red[t] = v * v;
    __syncthreads();
    #pragma unroll
    for (int s = DIM / 2; s > 0; s >>= 1) {
        if (t < s) red[t] += red[t + s];
        __syncthreads();
    }
    float nrm = fmaxf(sqrtf(red[0]), 1e-8f);   // torch clamp eps
    g_zn[(size_t)r * DIM + t] = v / nrm;
}

// ---------------------------------------------------------------------------
// Kernel 2: fused GEMM (Zn * Zn^T) + shifted exp-sum + target gather.
// Block handles 64 rows; loops over 64 column tiles of 128; K chunked by 64.
// Thread layout 16x16, thread tile 4(m) x 8(n).
// ---------------------------------------------------------------------------
__global__ void __launch_bounds__(256) fused_kernel() {
    // 48 KB static shared: As[KC][BM] (16KB, k-major) + Bs[KC][BN] (32KB, k-major)
    __shared__ __align__(16) float smem[KC * BM + KC * BN];
    float (*As)[BM] = reinterpret_cast<float(*)[BM]>(smem);
    float (*Bs)[BN] = reinterpret_cast<float(*)[BN]>(smem + KC * BM);
    // aliased AFTER all tile compute is done (guarded by __syncthreads):
    float* sRow = smem;        // [BM] per-row exp-sums
    float* sT   = smem + BM;   // [BM] per-row target dot

    const float* zn = g_zn;
    const int tid = threadIdx.x;
    const int tx  = tid & 15;        // n direction
    const int ty  = tid >> 4;        // m direction
    const int row0 = blockIdx.x * BM;
    const int m0 = ty * 4;
    const int n0 = tx * 8;

    float rowsum[4] = {0.f, 0.f, 0.f, 0.f};
    float tdot[4]   = {99.f, 99.f, 99.f, 99.f};   // sentinel; real dots are in [-1,1]

    const float C1 = 2.885390081777927f;          // 2 * log2(e)   (score = 2*dot)

    for (int jt = 0; jt < NTILES; ++jt) {
        const int col0 = jt * BN;
        float c[4][8];
        #pragma unroll
        for (int i = 0; i < 4; i++)
            #pragma unroll
            for (int j = 0; j < 8; j++) c[i][j] = 0.f;

        for (int kc = 0; kc < DIM; kc += KC) {
            // --- load A chunk, transposed to k-major: As[k][m] ---
            #pragma unroll
            for (int it = 0; it < (BM * (KC / 4)) / 256; ++it) {   // 4 iters
                int idx = it * 256 + tid;
                int m  = idx & (BM - 1);
                int kg = idx >> 6;                                  // idx / BM
                float4 v = *reinterpret_cast<const float4*>(
                    &zn[(size_t)(row0 + m) * DIM + kc + kg * 4]);
                As[kg * 4 + 0][m] = v.x;
                As[kg * 4 + 1][m] = v.y;
                As[kg * 4 + 2][m] = v.z;
                As[kg * 4 + 3][m] = v.w;
            }
            // --- load B chunk, transposed to k-major: Bs[k][n] ---
            #pragma unroll
            for (int it = 0; it < (BN * (KC / 4)) / 256; ++it) {   // 8 iters
                int idx = it * 256 + tid;
                int n  = idx & (BN - 1);
                int kg = idx >> 7;                                  // idx / BN
                float4 v = *reinterpret_cast<const float4*>(
                    &zn[(size_t)(col0 + n) * DIM + kc + kg * 4]);
                Bs[kg * 4 + 0][n] = v.x;
                Bs[kg * 4 + 1][n] = v.y;
                Bs[kg * 4 + 2][n] = v.z;
                Bs[kg * 4 + 3][n] = v.w;
            }
            __syncthreads();

            #pragma unroll 8
            for (int k = 0; k < KC; ++k) {
                float4 av = *reinterpret_cast<const float4*>(&As[k][m0]);
                float4 b0 = *reinterpret_cast<const float4*>(&Bs[k][n0]);
                float4 b1 = *reinterpret_cast<const float4*>(&Bs[k][n0 + 4]);
                float a[4] = {av.x, av.y, av.z, av.w};
                float b[8] = {b0.x, b0.y, b0.z, b0.w, b1.x, b1.y, b1.z, b1.w};
                #pragma unroll
                for (int i = 0; i < 4; i++)
                    #pragma unroll
                    for (int j = 0; j < 8; j++)
                        c[i][j] = fmaf(a[i], b[j], c[i][j]);
            }
            __syncthreads();
        }

        // --- epilogue: shifted exp-sum, skip diagonal, grab target dot ---
        #pragma unroll
        for (int i = 0; i < 4; i++) {
            const int grow = row0 + m0 + i;
            #pragma unroll
            for (int j = 0; j < 8; j++) {
                const int gcol = col0 + n0 + j;
                const float d = c[i][j];
                if (gcol != grow)
                    rowsum[i] += exp2f(fmaf(d, C1, -C1));  // exp(2d - 2)
                if (gcol == (grow ^ 1))
                    tdot[i] = d;
            }
        }
    }

    // --- per-row reduction across the 16 tx threads, then per-block loss ---
    __syncthreads();                 // all smem tile use finished; safe to alias
    if (tid < BM) sRow[tid] = 0.f;
    __syncthreads();
    #pragma unroll
    for (int i = 0; i < 4; i++) {
        atomicAdd(&sRow[m0 + i], rowsum[i]);
        if (tdot[i] < 50.f) sT[m0 + i] = tdot[i];   // unique owner per row
    }
    __syncthreads();
    if (tid == 0) {
        float tot = 0.f;
        for (int r = 0; r < BM; ++r)
            tot += 2.f + logf(sRow[r]) - 2.f * sT[r];   // LSE - s_target
        g_partial[blockIdx.x] = tot;
    }
}

// ---------------------------------------------------------------------------
// Kernel 3: final reduction -> mean loss.
// ---------------------------------------------------------------------------
__global__ void finalize_kernel(float* __restrict__ out) {
    __shared__ float s[NBLOCKS];
    int t = threadIdx.x;
    s[t] = g_partial[t];
    __syncthreads();
    #pragma unroll
    for (int st = NBLOCKS / 2; st > 0; st >>= 1) {
        if (t < st) s[t] += s[t + st];
        __syncthreads();
    }
    if (t == 0) out[0] = s[0] / (float)NROWS;
}

// ---------------------------------------------------------------------------
extern "C" void kernel_launch(void* const* d_in, const int* in_sizes, int n_in,
                              void* d_out, int out_size) {
    const float* zis = (const float*)d_in[0];
    const float* zjs = (const float*)d_in[1];
    float* out = (float*)d_out;

    normalize_kernel<<<NROWS, DIM>>>(zis, zjs);
    fused_kernel<<<NBLOCKS, 256>>>();
    finalize_kernel<<<1, NBLOCKS>>>(out);
}

// round 3
// speedup vs baseline: 15.9636x; 15.9636x over previous
#include <cuda_runtime.h>
#include <cuda_bf16.h>
#include <math.h>
#include <stdint.h>

// NT-Xent loss. N=8192 rows (interleaved zjs/zis), D=256.
// score = 2*cos(i,j); bounded in [-2,2] -> fixed-shift logsumexp:
//   loss_i = 2 + ln(sum_{j!=i} exp(2 d_ij - 2)) - 2 d_{i, i^1}
// GEMM via mma.sync bf16 (base sm_100 PTX; tcgen05 unavailable at this target).

#define NROWS 8192
#define DIM   256
#define BK    64

__device__ __align__(16) __nv_bfloat16 g_zn[NROWS * DIM];  // 4 MB normalized
__device__ float g_rowsum[NROWS];
__device__ float g_tdot[NROWS];

// ---------------- helpers ----------------
__device__ __forceinline__ uint32_t smem_u32(const void* p) {
    uint32_t a;
    asm("{ .reg .u64 t; cvta.to.shared.u64 t, %1; cvt.u32.u64 %0, t; }"
        : "=r"(a) : "l"(p));
    return a;
}
__device__ __forceinline__ void cp16(uint32_t dst, const void* src) {
    asm volatile("cp.async.cg.shared.global [%0], [%1], 16;"
                 :: "r"(dst), "l"(src) : "memory");
}
__device__ __forceinline__ void ldsm_x4(uint32_t* r, uint32_t addr) {
    asm volatile("ldmatrix.sync.aligned.m8n8.x4.shared.b16 {%0,%1,%2,%3}, [%4];"
                 : "=r"(r[0]), "=r"(r[1]), "=r"(r[2]), "=r"(r[3]) : "r"(addr));
}
__device__ __forceinline__ void mma16816(float* c, const uint32_t* a,
                                         uint32_t b0, uint32_t b1) {
    asm volatile("mma.sync.aligned.m16n8k16.row.col.f32.bf16.bf16.f32 "
                 "{%0,%1,%2,%3}, {%4,%5,%6,%7}, {%8,%9}, {%0,%1,%2,%3};"
                 : "+f"(c[0]), "+f"(c[1]), "+f"(c[2]), "+f"(c[3])
                 : "r"(a[0]), "r"(a[1]), "r"(a[2]), "r"(a[3]), "r"(b0), "r"(b1));
}
__device__ __forceinline__ float fexp2(float x) {
    float e; asm("ex2.approx.ftz.f32 %0, %1;" : "=f"(e) : "f"(x)); return e;
}

// ---------------------------------------------------------------------------
// Kernel 1: interleave + fp32 normalize -> bf16; zero g_rowsum.
// One warp per row; grid = 1024 x 256 threads.
// ---------------------------------------------------------------------------
__global__ void __launch_bounds__(256) normalize_kernel(
    const float* __restrict__ zis, const float* __restrict__ zjs) {
    int gtid = blockIdx.x * 256 + threadIdx.x;
    if (gtid < NROWS) g_rowsum[gtid] = 0.f;

    int w = threadIdx.x >> 5, lid = threadIdx.x & 31;
    int row = blockIdx.x * 8 + w;
    const float* src = (row & 1) ? (zis + (size_t)(row >> 1) * DIM)
                                 : (zjs + (size_t)(row >> 1) * DIM);
    float4 v0 = *reinterpret_cast<const float4*>(src + lid * 4);
    float4 v1 = *reinterpret_cast<const float4*>(src + 128 + lid * 4);
    float s = v0.x*v0.x + v0.y*v0.y + v0.z*v0.z + v0.w*v0.w
            + v1.x*v1.x + v1.y*v1.y + v1.z*v1.z + v1.w*v1.w;
    #pragma unroll
    for (int o = 16; o > 0; o >>= 1) s += __shfl_xor_sync(0xFFFFFFFF, s, o);
    float inv = 1.0f / fmaxf(sqrtf(s), 1e-8f);

    __nv_bfloat16* dst = g_zn + (size_t)row * DIM;
    __nv_bfloat162 p0 = __floats2bfloat162_rn(v0.x * inv, v0.y * inv);
    __nv_bfloat162 p1 = __floats2bfloat162_rn(v0.z * inv, v0.w * inv);
    __nv_bfloat162 p2 = __floats2bfloat162_rn(v1.x * inv, v1.y * inv);
    __nv_bfloat162 p3 = __floats2bfloat162_rn(v1.z * inv, v1.w * inv);
    uint2 a; a.x = *reinterpret_cast<uint32_t*>(&p0); a.y = *reinterpret_cast<uint32_t*>(&p1);
    uint2 b; b.x = *reinterpret_cast<uint32_t*>(&p2); b.y = *reinterpret_cast<uint32_t*>(&p3);
    *reinterpret_cast<uint2*>(dst + lid * 4) = a;
    *reinterpret_cast<uint2*>(dst + 128 + lid * 4) = b;
}

// ---------------------------------------------------------------------------
// Kernel 2: 128x128 bf16 mma.sync GEMM tile + fused shifted-exp epilogue.
// 8 warps (2m x 4n), warp tile 64x32.  SMEM: double-buffered A/B 64KB.
// Swizzle: rows of 128B (64 bf16), chunk16 XOR (row&7)<<4 -> conflict-free.
// ---------------------------------------------------------------------------
#define SMEM_TOTAL 65536

__global__ void __launch_bounds__(256, 2) gemm_kernel() {
    extern __shared__ __align__(16) char smem[];
    const uint32_t sb = smem_u32(smem);
    const int tid = threadIdx.x;
    const int lid = tid & 31;
    const int wid = tid >> 5;
    const int wm = wid >> 2;              // 0..1
    const int wn = wid & 3;               // 0..3
    const int wrow = wm * 64;
    const int wcol = wn * 32;
    const int row0 = blockIdx.y * 128;
    const int col0 = blockIdx.x * 128;
    const bool diag = (blockIdx.x == blockIdx.y);

    float c[4][4][4];
    #pragma unroll
    for (int mi = 0; mi < 4; mi++)
        #pragma unroll
        for (int ni = 0; ni < 4; ni++)
            #pragma unroll
            for (int q = 0; q < 4; q++) c[mi][ni][q] = 0.f;

    const char* gA = (const char*)g_zn + (size_t)row0 * 512;
    const char* gB = (const char*)g_zn + (size_t)col0 * 512;

    // ---- stage loader: A/B chunk (128 rows x 64 bf16 = 16KB each) ----
    auto load_stage = [&](int ch, int s) {
        uint32_t dA = sb + (uint32_t)s * 32768u;
        uint32_t dB = dA + 16384u;
        const char* srcA = gA + ch * 128;
        const char* srcB = gB + ch * 128;
        #pragma unroll
        for (int it = 0; it < 4; it++) {
            int i = it * 256 + tid;          // 0..1023
            int r = i >> 3, g = i & 7;
            uint32_t off = (uint32_t)(r * 128 + ((g * 16) ^ ((r & 7) << 4)));
            cp16(dA + off, srcA + (size_t)r * 512 + g * 16);
        }
        #pragma unroll
        for (int it = 0; it < 4; it++) {
            int i = it * 256 + tid;
            int r = i >> 3, g = i & 7;
            uint32_t off = (uint32_t)(r * 128 + ((g * 16) ^ ((r & 7) << 4)));
            cp16(dB + off, srcB + (size_t)r * 512 + g * 16);
        }
        asm volatile("cp.async.commit_group;" ::: "memory");
    };

    const int lg = lid & 7;               // ldmatrix row within 8x8 tile
    const int ltile = lid >> 3;           // which of 4 tiles
    const int trow8 = (ltile & 1) * 8;    // +8 rows for tiles 1,3
    const int tk16 = (ltile >> 1) * 16;   // +16B (k 8-15) for tiles 2,3

    auto compute = [&](int s) {
        uint32_t asb = sb + (uint32_t)s * 32768u;
        uint32_t bsb = asb + 16384u;
        #pragma unroll
        for (int k16 = 0; k16 < 4; k16++) {
            int kb = k16 * 32 + tk16;
            uint32_t a[4][4], bb[2][4];
            #pragma unroll
            for (int mi = 0; mi < 4; mi++) {
                int m = wrow + mi * 16 + trow8 + lg;
                ldsm_x4(a[mi], asb + (uint32_t)(m * 128 + (kb ^ ((m & 7) << 4))));
            }
            #pragma unroll
            for (int nb = 0; nb < 2; nb++) {
                int n = wcol + nb * 16 + trow8 + lg;
                ldsm_x4(bb[nb], bsb + (uint32_t)(n * 128 + (kb ^ ((n & 7) << 4))));
            }
            #pragma unroll
            for (int mi = 0; mi < 4; mi++) {
                #pragma unroll
                for (int ni = 0; ni < 4; ni++) {
                    const uint32_t* B = bb[ni >> 1];
                    uint32_t b0 = (ni & 1) ? B[1] : B[0];
                    uint32_t b1 = (ni & 1) ? B[3] : B[2];
                    mma16816(c[mi][ni], a[mi], b0, b1);
                }
            }
        }
    };

    // ---- pipelined main loop over 4 K-chunks ----
    load_stage(0, 0);
    #pragma unroll
    for (int ch = 0; ch < 4; ch++) {
        if (ch < 3) {
            load_stage(ch + 1, (ch + 1) & 1);
            asm volatile("cp.async.wait_group 1;" ::: "memory");
        } else {
            asm volatile("cp.async.wait_group 0;" ::: "memory");
        }
        __syncthreads();
        compute(ch & 1);
        __syncthreads();
    }

    // ---- epilogue: shifted exp-sum per row ----
    const float C1 = 2.885390081777927f;   // 2*log2(e)
    float* srow = (float*)smem;            // reuse smem as [128] row sums
    if (tid < 128) srow[tid] = 0.f;
    __syncthreads();

    float rs[4][2];
    #pragma unroll
    for (int mi = 0; mi < 4; mi++) { rs[mi][0] = 0.f; rs[mi][1] = 0.f; }

    #pragma unroll
    for (int mi = 0; mi < 4; mi++) {
        int r0 = row0 + wrow + mi * 16 + (lid >> 2);   // rows for c0,c1
        int r1 = r0 + 8;                                // rows for c2,c3
        #pragma unroll
        for (int ni = 0; ni < 4; ni++) {
            int cb = col0 + wcol + ni * 8 + (lid & 3) * 2;
            float d0 = c[mi][ni][0], d1 = c[mi][ni][1];
            float d2 = c[mi][ni][2], d3 = c[mi][ni][3];
            float e0 = fexp2(fmaf(d0, C1, -C1));
            float e1 = fexp2(fmaf(d1, C1, -C1));
            float e2 = fexp2(fmaf(d2, C1, -C1));
            float e3 = fexp2(fmaf(d3, C1, -C1));
            if (diag) {
                if (cb     == r0) e0 = 0.f;
                if (cb + 1 == r0) e1 = 0.f;
                if (cb     == r1) e2 = 0.f;
                if (cb + 1 == r1) e3 = 0.f;
                if (cb     == (r0 ^ 1)) g_tdot[r0] = d0;
                if (cb + 1 == (r0 ^ 1)) g_tdot[r0] = d1;
                if (cb     == (r1 ^ 1)) g_tdot[r1] = d2;
                if (cb + 1 == (r1 ^ 1)) g_tdot[r1] = d3;
            }
            rs[mi][0] += e0 + e1;
            rs[mi][1] += e2 + e3;
        }
    }
    // reduce across the 4 lanes sharing each row (lid&3)
    #pragma unroll
    for (int mi = 0; mi < 4; mi++) {
        #pragma unroll
        for (int h = 0; h < 2; h++) {
            rs[mi][h] += __shfl_xor_sync(0xFFFFFFFF, rs[mi][h], 1);
            rs[mi][h] += __shfl_xor_sync(0xFFFFFFFF, rs[mi][h], 2);
        }
    }
    if ((lid & 3) == 0) {
        int rl = wrow + (lid >> 2);
        #pragma unroll
        for (int mi = 0; mi < 4; mi++) {
            atomicAdd(&srow[rl + mi * 16],     rs[mi][0]);
            atomicAdd(&srow[rl + mi * 16 + 8], rs[mi][1]);
        }
    }
    __syncthreads();
    if (tid < 128) atomicAdd(&g_rowsum[row0 + tid], srow[tid]);
}

// ---------------------------------------------------------------------------
// Kernel 3: final reduction -> mean loss.
// ---------------------------------------------------------------------------
__global__ void __launch_bounds__(1024) finalize_kernel(float* __restrict__ out) {
    float acc = 0.f;
    for (int r = threadIdx.x; r < NROWS; r += 1024)
        acc += 2.f + logf(g_rowsum[r]) - 2.f * g_tdot[r];
    #pragma unroll
    for (int o = 16; o > 0; o >>= 1) acc += __shfl_xor_sync(0xFFFFFFFF, acc, o);
    __shared__ float sh[32];
    int w = threadIdx.x >> 5, l = threadIdx.x & 31;
    if (l == 0) sh[w] = acc;
    __syncthreads();
    if (w == 0) {
        float v = sh[l];
        #pragma unroll
        for (int o = 16; o > 0; o >>= 1) v += __shfl_xor_sync(0xFFFFFFFF, v, o);
        if (l == 0) out[0] = v / (float)NROWS;
    }
}

// ---------------------------------------------------------------------------
extern "C" void kernel_launch(void* const* d_in, const int* in_sizes, int n_in,
                              void* d_out, int out_size) {
    const float* zis = (const float*)d_in[0];
    const float* zjs = (const float*)d_in[1];
    float* out = (float*)d_out;

    cudaFuncSetAttribute(gemm_kernel,
                         cudaFuncAttributeMaxDynamicSharedMemorySize, SMEM_TOTAL);

    normalize_kernel<<<NROWS / 8, 256>>>(zis, zjs);
    dim3 grid(64, 64);
    gemm_kernel<<<grid, 256, SMEM_TOTAL>>>();
    finalize_kernel<<<1, 1024>>>(out);
}

// round 4
// speedup vs baseline: 24.9205x; 1.5611x over previous
#include <cuda_runtime.h>
#include <cuda_bf16.h>
#include <math.h>
#include <stdint.h>

// NT-Xent loss. N=8192 rows (interleaved zjs/zis), D=256.
// score = 2*cos(i,j) in [-2,2] -> fixed-shift logsumexp:
//   loss_i = 2 + ln(sum_{j!=i} exp(2 d_ij - 2)) - 2 d_{i, i^1}
// Symmetric GEMM: compute only upper-triangle 128x128 tiles; each off-diag
// tile feeds exp-sums to BOTH its rows and its columns.

#define NROWS 8192
#define DIM   256

__device__ __align__(16) __nv_bfloat16 g_zn[NROWS * DIM];  // 4 MB normalized
__device__ float g_rowsum[NROWS];
__device__ float g_tdot[NROWS];

// ---------------- helpers ----------------
__device__ __forceinline__ uint32_t smem_u32(const void* p) {
    uint32_t a;
    asm("{ .reg .u64 t; cvta.to.shared.u64 t, %1; cvt.u32.u64 %0, t; }"
        : "=r"(a) : "l"(p));
    return a;
}
__device__ __forceinline__ void cp16(uint32_t dst, const void* src) {
    asm volatile("cp.async.cg.shared.global [%0], [%1], 16;"
                 :: "r"(dst), "l"(src) : "memory");
}
__device__ __forceinline__ void ldsm_x4(uint32_t* r, uint32_t addr) {
    asm volatile("ldmatrix.sync.aligned.m8n8.x4.shared.b16 {%0,%1,%2,%3}, [%4];"
                 : "=r"(r[0]), "=r"(r[1]), "=r"(r[2]), "=r"(r[3]) : "r"(addr));
}
__device__ __forceinline__ void mma16816(float* c, const uint32_t* a,
                                         uint32_t b0, uint32_t b1) {
    asm volatile("mma.sync.aligned.m16n8k16.row.col.f32.bf16.bf16.f32 "
                 "{%0,%1,%2,%3}, {%4,%5,%6,%7}, {%8,%9}, {%0,%1,%2,%3};"
                 : "+f"(c[0]), "+f"(c[1]), "+f"(c[2]), "+f"(c[3])
                 : "r"(a[0]), "r"(a[1]), "r"(a[2]), "r"(a[3]), "r"(b0), "r"(b1));
}
__device__ __forceinline__ float fexp2(float x) {
    float e; asm("ex2.approx.ftz.f32 %0, %1;" : "=f"(e) : "f"(x)); return e;
}

// ---------------------------------------------------------------------------
// Kernel 1: interleave + fp32 normalize -> bf16; zero g_rowsum.
// ---------------------------------------------------------------------------
__global__ void __launch_bounds__(256) normalize_kernel(
    const float* __restrict__ zis, const float* __restrict__ zjs) {
    int gtid = blockIdx.x * 256 + threadIdx.x;
    if (gtid < NROWS) g_rowsum[gtid] = 0.f;

    int w = threadIdx.x >> 5, lid = threadIdx.x & 31;
    int row = blockIdx.x * 8 + w;
    const float* src = (row & 1) ? (zis + (size_t)(row >> 1) * DIM)
                                 : (zjs + (size_t)(row >> 1) * DIM);
    float4 v0 = *reinterpret_cast<const float4*>(src + lid * 4);
    float4 v1 = *reinterpret_cast<const float4*>(src + 128 + lid * 4);
    float s = v0.x*v0.x + v0.y*v0.y + v0.z*v0.z + v0.w*v0.w
            + v1.x*v1.x + v1.y*v1.y + v1.z*v1.z + v1.w*v1.w;
    #pragma unroll
    for (int o = 16; o > 0; o >>= 1) s += __shfl_xor_sync(0xFFFFFFFF, s, o);
    float inv = 1.0f / fmaxf(sqrtf(s), 1e-8f);

    __nv_bfloat16* dst = g_zn + (size_t)row * DIM;
    __nv_bfloat162 p0 = __floats2bfloat162_rn(v0.x * inv, v0.y * inv);
    __nv_bfloat162 p1 = __floats2bfloat162_rn(v0.z * inv, v0.w * inv);
    __nv_bfloat162 p2 = __floats2bfloat162_rn(v1.x * inv, v1.y * inv);
    __nv_bfloat162 p3 = __floats2bfloat162_rn(v1.z * inv, v1.w * inv);
    uint2 a; a.x = *reinterpret_cast<uint32_t*>(&p0); a.y = *reinterpret_cast<uint32_t*>(&p1);
    uint2 b; b.x = *reinterpret_cast<uint32_t*>(&p2); b.y = *reinterpret_cast<uint32_t*>(&p3);
    *reinterpret_cast<uint2*>(dst + lid * 4) = a;
    *reinterpret_cast<uint2*>(dst + 128 + lid * 4) = b;
}

// ---------------------------------------------------------------------------
// Kernel 2: upper-triangle 128x128 bf16 mma.sync tiles + symmetric epilogue.
// 8 warps (2m x 4n), warp tile 64x32. Double-buffered smem (64 KB).
// ---------------------------------------------------------------------------
#define SMEM_TOTAL 65536

__global__ void __launch_bounds__(256, 2) gemm_kernel() {
    const int bx = blockIdx.x, by = blockIdx.y;
    if (bx < by) return;                    // lower triangle: skip (symmetry)
    const bool diag = (bx == by);

    extern __shared__ __align__(16) char smem[];
    const uint32_t sb = smem_u32(smem);
    const int tid = threadIdx.x;
    const int lid = tid & 31;
    const int wid = tid >> 5;
    const int wm = wid >> 2;              // 0..1
    const int wn = wid & 3;               // 0..3
    const int wrow = wm * 64;
    const int wcol = wn * 32;
    const int row0 = by * 128;
    const int col0 = bx * 128;

    float c[4][4][4];
    #pragma unroll
    for (int mi = 0; mi < 4; mi++)
        #pragma unroll
        for (int ni = 0; ni < 4; ni++)
            #pragma unroll
            for (int q = 0; q < 4; q++) c[mi][ni][q] = 0.f;

    const char* gA = (const char*)g_zn + (size_t)row0 * 512;
    const char* gB = (const char*)g_zn + (size_t)col0 * 512;

    // ---- stage loader: A (+B if offdiag) chunk, 128 rows x 64 bf16 each ----
    auto load_stage = [&](int ch, int s) {
        uint32_t dA = sb + (uint32_t)s * 32768u;
        const char* srcA = gA + ch * 128;
        #pragma unroll
        for (int it = 0; it < 4; it++) {
            int i = it * 256 + tid;          // 0..1023
            int r = i >> 3, g = i & 7;
            uint32_t off = (uint32_t)(r * 128 + ((g * 16) ^ ((r & 7) << 4)));
            cp16(dA + off, srcA + (size_t)r * 512 + g * 16);
        }
        if (!diag) {
            uint32_t dB = dA + 16384u;
            const char* srcB = gB + ch * 128;
            #pragma unroll
            for (int it = 0; it < 4; it++) {
                int i = it * 256 + tid;
                int r = i >> 3, g = i & 7;
                uint32_t off = (uint32_t)(r * 128 + ((g * 16) ^ ((r & 7) << 4)));
                cp16(dB + off, srcB + (size_t)r * 512 + g * 16);
            }
        }
        asm volatile("cp.async.commit_group;" ::: "memory");
    };

    const int lg = lid & 7;
    const int ltile = lid >> 3;
    const int trow8 = (ltile & 1) * 8;
    const int tk16 = (ltile >> 1) * 16;

    auto compute = [&](int s) {
        uint32_t asb = sb + (uint32_t)s * 32768u;
        uint32_t bsb = diag ? asb : (asb + 16384u);
        #pragma unroll
        for (int k16 = 0; k16 < 4; k16++) {
            int kb = k16 * 32 + tk16;
            uint32_t a[4][4], bb[2][4];
            #pragma unroll
            for (int mi = 0; mi < 4; mi++) {
                int m = wrow + mi * 16 + trow8 + lg;
                ldsm_x4(a[mi], asb + (uint32_t)(m * 128 + (kb ^ ((m & 7) << 4))));
            }
            #pragma unroll
            for (int nb = 0; nb < 2; nb++) {
                int n = wcol + nb * 16 + trow8 + lg;
                ldsm_x4(bb[nb], bsb + (uint32_t)(n * 128 + (kb ^ ((n & 7) << 4))));
            }
            #pragma unroll
            for (int mi = 0; mi < 4; mi++) {
                #pragma unroll
                for (int ni = 0; ni < 4; ni++) {
                    const uint32_t* B = bb[ni >> 1];
                    uint32_t b0 = (ni & 1) ? B[1] : B[0];
                    uint32_t b1 = (ni & 1) ? B[3] : B[2];
                    mma16816(c[mi][ni], a[mi], b0, b1);
                }
            }
        }
    };

    // ---- pipelined main loop over 4 K-chunks ----
    load_stage(0, 0);
    #pragma unroll
    for (int ch = 0; ch < 4; ch++) {
        if (ch < 3) {
            load_stage(ch + 1, (ch + 1) & 1);
            asm volatile("cp.async.wait_group 1;" ::: "memory");
        } else {
            asm volatile("cp.async.wait_group 0;" ::: "memory");
        }
        __syncthreads();
        compute(ch & 1);
        __syncthreads();
    }

    // ---- epilogue ----
    const float C1 = 2.885390081777927f;   // 2*log2(e)
    float* srow = (float*)smem;            // [128] row exp-sums
    float* scol = srow + 128;              // [128] col exp-sums (offdiag)
    if (tid < 256) srow[tid] = 0.f;        // zeros both arrays
    __syncthreads();

    float rs[4][2];
    float cs[4][2];
    #pragma unroll
    for (int i = 0; i < 4; i++) { rs[i][0]=rs[i][1]=0.f; cs[i][0]=cs[i][1]=0.f; }

    #pragma unroll
    for (int mi = 0; mi < 4; mi++) {
        int r0 = row0 + wrow + mi * 16 + (lid >> 2);
        int r1 = r0 + 8;
        #pragma unroll
        for (int ni = 0; ni < 4; ni++) {
            int cb = col0 + wcol + ni * 8 + (lid & 3) * 2;
            float d0 = c[mi][ni][0], d1 = c[mi][ni][1];
            float d2 = c[mi][ni][2], d3 = c[mi][ni][3];
            float e0 = fexp2(fmaf(d0, C1, -C1));
            float e1 = fexp2(fmaf(d1, C1, -C1));
            float e2 = fexp2(fmaf(d2, C1, -C1));
            float e3 = fexp2(fmaf(d3, C1, -C1));
            if (diag) {
                if (cb     == r0) e0 = 0.f;
                if (cb + 1 == r0) e1 = 0.f;
                if (cb     == r1) e2 = 0.f;
                if (cb + 1 == r1) e3 = 0.f;
                if (cb     == (r0 ^ 1)) g_tdot[r0] = d0;
                if (cb + 1 == (r0 ^ 1)) g_tdot[r0] = d1;
                if (cb     == (r1 ^ 1)) g_tdot[r1] = d2;
                if (cb + 1 == (r1 ^ 1)) g_tdot[r1] = d3;
            }
            rs[mi][0] += e0 + e1;
            rs[mi][1] += e2 + e3;
            cs[ni][0] += e0 + e2;     // column cb
            cs[ni][1] += e1 + e3;     // column cb+1
        }
    }

    // rows: reduce across the 4 lanes sharing each row
    #pragma unroll
    for (int mi = 0; mi < 4; mi++) {
        #pragma unroll
        for (int h = 0; h < 2; h++) {
            rs[mi][h] += __shfl_xor_sync(0xFFFFFFFF, rs[mi][h], 1);
            rs[mi][h] += __shfl_xor_sync(0xFFFFFFFF, rs[mi][h], 2);
        }
    }
    if ((lid & 3) == 0) {
        int rl = wrow + (lid >> 2);
        #pragma unroll
        for (int mi = 0; mi < 4; mi++) {
            atomicAdd(&srow[rl + mi * 16],     rs[mi][0]);
            atomicAdd(&srow[rl + mi * 16 + 8], rs[mi][1]);
        }
    }
    // cols (offdiag only): reduce across the 8 lanes sharing each column pair
    if (!diag) {
        #pragma unroll
        for (int ni = 0; ni < 4; ni++) {
            #pragma unroll
            for (int h = 0; h < 2; h++) {
                cs[ni][h] += __shfl_xor_sync(0xFFFFFFFF, cs[ni][h], 4);
                cs[ni][h] += __shfl_xor_sync(0xFFFFFFFF, cs[ni][h], 8);
                cs[ni][h] += __shfl_xor_sync(0xFFFFFFFF, cs[ni][h], 16);
            }
        }
        if (lid < 4) {
            #pragma unroll
            for (int ni = 0; ni < 4; ni++) {
                int cl = wcol + ni * 8 + lid * 2;
                atomicAdd(&scol[cl],     cs[ni][0]);
                atomicAdd(&scol[cl + 1], cs[ni][1]);
            }
        }
    }
    __syncthreads();
    if (tid < 128) {
        atomicAdd(&g_rowsum[row0 + tid], srow[tid]);
    } else if (!diag) {
        atomicAdd(&g_rowsum[col0 + tid - 128], scol[tid - 128]);
    }
}

// ---------------------------------------------------------------------------
// Kernel 3: final reduction -> mean loss.
// ---------------------------------------------------------------------------
__global__ void __launch_bounds__(1024) finalize_kernel(float* __restrict__ out) {
    float acc = 0.f;
    for (int r = threadIdx.x; r < NROWS; r += 1024)
        acc += 2.f + logf(g_rowsum[r]) - 2.f * g_tdot[r];
    #pragma unroll
    for (int o = 16; o > 0; o >>= 1) acc += __shfl_xor_sync(0xFFFFFFFF, acc, o);
    __shared__ float sh[32];
    int w = threadIdx.x >> 5, l = threadIdx.x & 31;
    if (l == 0) sh[w] = acc;
    __syncthreads();
    if (w == 0) {
        float v = sh[l];
        #pragma unroll
        for (int o = 16; o > 0; o >>= 1) v += __shfl_xor_sync(0xFFFFFFFF, v, o);
        if (l == 0) out[0] = v / (float)NROWS;
    }
}

// ---------------------------------------------------------------------------
extern "C" void kernel_launch(void* const* d_in, const int* in_sizes, int n_in,
                              void* d_out, int out_size) {
    const float* zis = (const float*)d_in[0];
    const float* zjs = (const float*)d_in[1];
    float* out = (float*)d_out;

    cudaFuncSetAttribute(gemm_kernel,
                         cudaFuncAttributeMaxDynamicSharedMemorySize, SMEM_TOTAL);

    normalize_kernel<<<NROWS / 8, 256>>>(zis, zjs);
    dim3 grid(64, 64);
    gemm_kernel<<<grid, 256, SMEM_TOTAL>>>();
    finalize_kernel<<<1, 1024>>>(out);
}

// round 5
// speedup vs baseline: 25.8031x; 1.0354x over previous
#include <cuda_runtime.h>
#include <cuda_bf16.h>
#include <math.h>
#include <stdint.h>

// NT-Xent loss. N=8192 rows (interleaved zjs/zis), D=256.
// score = 2*cos(i,j) in [-2,2] -> fixed-shift logsumexp:
//   loss_i = 2 + ln(sum_{j!=i} exp(2 d_ij - 2)) - 2 d_{i, i^1}
// Symmetric GEMM, exact triangular grid (2080 CTAs), 3-stage cp.async
// pipeline with a single __syncthreads per K-chunk.

#define NROWS 8192
#define DIM   256

__device__ __align__(16) __nv_bfloat16 g_zn[NROWS * DIM];  // 4 MB normalized
__device__ float g_rowsum[NROWS];
__device__ float g_tdot[NROWS];

// ---------------- helpers ----------------
__device__ __forceinline__ uint32_t smem_u32(const void* p) {
    uint32_t a;
    asm("{ .reg .u64 t; cvta.to.shared.u64 t, %1; cvt.u32.u64 %0, t; }"
        : "=r"(a) : "l"(p));
    return a;
}
__device__ __forceinline__ void cp16(uint32_t dst, const void* src) {
    asm volatile("cp.async.cg.shared.global [%0], [%1], 16;"
                 :: "r"(dst), "l"(src) : "memory");
}
__device__ __forceinline__ void ldsm_x4(uint32_t* r, uint32_t addr) {
    asm volatile("ldmatrix.sync.aligned.m8n8.x4.shared.b16 {%0,%1,%2,%3}, [%4];"
                 : "=r"(r[0]), "=r"(r[1]), "=r"(r[2]), "=r"(r[3]) : "r"(addr));
}
__device__ __forceinline__ void mma16816(float* c, const uint32_t* a,
                                         uint32_t b0, uint32_t b1) {
    asm volatile("mma.sync.aligned.m16n8k16.row.col.f32.bf16.bf16.f32 "
                 "{%0,%1,%2,%3}, {%4,%5,%6,%7}, {%8,%9}, {%0,%1,%2,%3};"
                 : "+f"(c[0]), "+f"(c[1]), "+f"(c[2]), "+f"(c[3])
                 : "r"(a[0]), "r"(a[1]), "r"(a[2]), "r"(a[3]), "r"(b0), "r"(b1));
}
__device__ __forceinline__ float fexp2(float x) {
    float e; asm("ex2.approx.ftz.f32 %0, %1;" : "=f"(e) : "f"(x)); return e;
}

// ---------------------------------------------------------------------------
// Kernel 1: interleave + fp32 normalize -> bf16; zero g_rowsum.
// ---------------------------------------------------------------------------
__global__ void __launch_bounds__(256) normalize_kernel(
    const float* __restrict__ zis, const float* __restrict__ zjs) {
    int gtid = blockIdx.x * 256 + threadIdx.x;
    if (gtid < NROWS) g_rowsum[gtid] = 0.f;

    int w = threadIdx.x >> 5, lid = threadIdx.x & 31;
    int row = blockIdx.x * 8 + w;
    const float* src = (row & 1) ? (zis + (size_t)(row >> 1) * DIM)
                                 : (zjs + (size_t)(row >> 1) * DIM);
    float4 v0 = *reinterpret_cast<const float4*>(src + lid * 4);
    float4 v1 = *reinterpret_cast<const float4*>(src + 128 + lid * 4);
    float s = v0.x*v0.x + v0.y*v0.y + v0.z*v0.z + v0.w*v0.w
            + v1.x*v1.x + v1.y*v1.y + v1.z*v1.z + v1.w*v1.w;
    #pragma unroll
    for (int o = 16; o > 0; o >>= 1) s += __shfl_xor_sync(0xFFFFFFFF, s, o);
    float inv = 1.0f / fmaxf(sqrtf(s), 1e-8f);

    __nv_bfloat16* dst = g_zn + (size_t)row * DIM;
    __nv_bfloat162 p0 = __floats2bfloat162_rn(v0.x * inv, v0.y * inv);
    __nv_bfloat162 p1 = __floats2bfloat162_rn(v0.z * inv, v0.w * inv);
    __nv_bfloat162 p2 = __floats2bfloat162_rn(v1.x * inv, v1.y * inv);
    __nv_bfloat162 p3 = __floats2bfloat162_rn(v1.z * inv, v1.w * inv);
    uint2 a; a.x = *reinterpret_cast<uint32_t*>(&p0); a.y = *reinterpret_cast<uint32_t*>(&p1);
    uint2 b; b.x = *reinterpret_cast<uint32_t*>(&p2); b.y = *reinterpret_cast<uint32_t*>(&p3);
    *reinterpret_cast<uint2*>(dst + lid * 4) = a;
    *reinterpret_cast<uint2*>(dst + 128 + lid * 4) = b;
}

// ---------------------------------------------------------------------------
// Kernel 2: upper-triangle 128x128 bf16 mma.sync tiles + symmetric epilogue.
// grid (65, 32) packs the 2080-tile triangle exactly.
// 8 warps (2m x 4n), warp tile 64x32. 3-stage cp.async smem (96 KB).
// ---------------------------------------------------------------------------
#define SMEM_TOTAL 98304

__global__ void __launch_bounds__(256, 2) gemm_kernel() {
    // triangular decode: pair row y (len 64-y) with row 63-y (len y+1)
    const int x = blockIdx.x, y = blockIdx.y;   // x in [0,65), y in [0,32)
    int by, bx;
    if (x < 64 - y) { by = y;      bx = y + x; }
    else            { by = 63 - y; bx = x - 1; }
    const bool diag = (bx == by);

    extern __shared__ __align__(16) char smem[];
    const uint32_t sb = smem_u32(smem);
    const int tid = threadIdx.x;
    const int lid = tid & 31;
    const int wid = tid >> 5;
    const int wm = wid >> 2;              // 0..1
    const int wn = wid & 3;               // 0..3
    const int wrow = wm * 64;
    const int wcol = wn * 32;
    const int row0 = by * 128;
    const int col0 = bx * 128;

    float c[4][4][4];
    #pragma unroll
    for (int mi = 0; mi < 4; mi++)
        #pragma unroll
        for (int ni = 0; ni < 4; ni++)
            #pragma unroll
            for (int q = 0; q < 4; q++) c[mi][ni][q] = 0.f;

    const char* gA = (const char*)g_zn + (size_t)row0 * 512;
    const char* gB = (const char*)g_zn + (size_t)col0 * 512;

    // ---- stage loader: A (+B if offdiag) chunk into stage s (32 KB) ----
    auto load_stage = [&](int ch, int s) {
        uint32_t dA = sb + (uint32_t)s * 32768u;
        const char* srcA = gA + ch * 128;
        #pragma unroll
        for (int it = 0; it < 4; it++) {
            int i = it * 256 + tid;          // 0..1023
            int r = i >> 3, g = i & 7;
            uint32_t off = (uint32_t)(r * 128 + ((g * 16) ^ ((r & 7) << 4)));
            cp16(dA + off, srcA + (size_t)r * 512 + g * 16);
        }
        if (!diag) {
            uint32_t dB = dA + 16384u;
            const char* srcB = gB + ch * 128;
            #pragma unroll
            for (int it = 0; it < 4; it++) {
                int i = it * 256 + tid;
                int r = i >> 3, g = i & 7;
                uint32_t off = (uint32_t)(r * 128 + ((g * 16) ^ ((r & 7) << 4)));
                cp16(dB + off, srcB + (size_t)r * 512 + g * 16);
            }
        }
        asm volatile("cp.async.commit_group;" ::: "memory");
    };

    const int lg = lid & 7;
    const int ltile = lid >> 3;
    const int trow8 = (ltile & 1) * 8;
    const int tk16 = (ltile >> 1) * 16;

    auto compute = [&](int s) {
        uint32_t asb = sb + (uint32_t)s * 32768u;
        uint32_t bsb = diag ? asb : (asb + 16384u);
        #pragma unroll
        for (int k16 = 0; k16 < 4; k16++) {
            int kb = k16 * 32 + tk16;
            uint32_t a[4][4], bb[2][4];
            #pragma unroll
            for (int mi = 0; mi < 4; mi++) {
                int m = wrow + mi * 16 + trow8 + lg;
                ldsm_x4(a[mi], asb + (uint32_t)(m * 128 + (kb ^ ((m & 7) << 4))));
            }
            #pragma unroll
            for (int nb = 0; nb < 2; nb++) {
                int n = wcol + nb * 16 + trow8 + lg;
                ldsm_x4(bb[nb], bsb + (uint32_t)(n * 128 + (kb ^ ((n & 7) << 4))));
            }
            #pragma unroll
            for (int mi = 0; mi < 4; mi++) {
                #pragma unroll
                for (int ni = 0; ni < 4; ni++) {
                    const uint32_t* B = bb[ni >> 1];
                    uint32_t b0 = (ni & 1) ? B[1] : B[0];
                    uint32_t b1 = (ni & 1) ? B[3] : B[2];
                    mma16816(c[mi][ni], a[mi], b0, b1);
                }
            }
        }
    };

    // ---- 3-stage pipeline over 4 K-chunks, one sync per chunk ----
    load_stage(0, 0);
    load_stage(1, 1);
    #pragma unroll
    for (int ch = 0; ch < 4; ch++) {
        if (ch < 3) asm volatile("cp.async.wait_group 1;" ::: "memory");
        else        asm volatile("cp.async.wait_group 0;" ::: "memory");
        __syncthreads();
        // all warps finished compute(ch-1) before this sync -> buffer
        // (ch+2)%3 == (ch-1)%3 is free to overwrite
        if (ch < 2) load_stage(ch + 2, (ch + 2) % 3);
        compute(ch % 3);
    }
    __syncthreads();   // compute done in all warps before smem reuse

    // ---- epilogue ----
    const float C1 = 2.885390081777927f;   // 2*log2(e)
    float* srow = (float*)smem;            // [128] row exp-sums
    float* scol = srow + 128;              // [128] col exp-sums (offdiag)
    if (tid < 256) srow[tid] = 0.f;        // zeros both arrays
    __syncthreads();

    float rs[4][2];
    float cs[4][2];
    #pragma unroll
    for (int i = 0; i < 4; i++) { rs[i][0]=rs[i][1]=0.f; cs[i][0]=cs[i][1]=0.f; }

    #pragma unroll
    for (int mi = 0; mi < 4; mi++) {
        int r0 = row0 + wrow + mi * 16 + (lid >> 2);
        int r1 = r0 + 8;
        #pragma unroll
        for (int ni = 0; ni < 4; ni++) {
            int cb = col0 + wcol + ni * 8 + (lid & 3) * 2;
            float d0 = c[mi][ni][0], d1 = c[mi][ni][1];
            float d2 = c[mi][ni][2], d3 = c[mi][ni][3];
            float e0 = fexp2(fmaf(d0, C1, -C1));
            float e1 = fexp2(fmaf(d1, C1, -C1));
            float e2 = fexp2(fmaf(d2, C1, -C1));
            float e3 = fexp2(fmaf(d3, C1, -C1));
            if (diag) {
                if (cb     == r0) e0 = 0.f;
                if (cb + 1 == r0) e1 = 0.f;
                if (cb     == r1) e2 = 0.f;
                if (cb + 1 == r1) e3 = 0.f;
                if (cb     == (r0 ^ 1)) g_tdot[r0] = d0;
                if (cb + 1 == (r0 ^ 1)) g_tdot[r0] = d1;
                if (cb     == (r1 ^ 1)) g_tdot[r1] = d2;
                if (cb + 1 == (r1 ^ 1)) g_tdot[r1] = d3;
            }
            rs[mi][0] += e0 + e1;
            rs[mi][1] += e2 + e3;
            cs[ni][0] += e0 + e2;     // column cb
            cs[ni][1] += e1 + e3;     // column cb+1
        }
    }

    // rows: reduce across the 4 lanes sharing each row
    #pragma unroll
    for (int mi = 0; mi < 4; mi++) {
        #pragma unroll
        for (int h = 0; h < 2; h++) {
            rs[mi][h] += __shfl_xor_sync(0xFFFFFFFF, rs[mi][h], 1);
            rs[mi][h] += __shfl_xor_sync(0xFFFFFFFF, rs[mi][h], 2);
        }
    }
    if ((lid & 3) == 0) {
        int rl = wrow + (lid >> 2);
        #pragma unroll
        for (int mi = 0; mi < 4; mi++) {
            atomicAdd(&srow[rl + mi * 16],     rs[mi][0]);
            atomicAdd(&srow[rl + mi * 16 + 8], rs[mi][1]);
        }
    }
    // cols (offdiag only): reduce across the 8 lanes sharing each column pair
    if (!diag) {
        #pragma unroll
        for (int ni = 0; ni < 4; ni++) {
            #pragma unroll
            for (int h = 0; h < 2; h++) {
                cs[ni][h] += __shfl_xor_sync(0xFFFFFFFF, cs[ni][h], 4);
                cs[ni][h] += __shfl_xor_sync(0xFFFFFFFF, cs[ni][h], 8);
                cs[ni][h] += __shfl_xor_sync(0xFFFFFFFF, cs[ni][h], 16);
            }
        }
        if (lid < 4) {
            #pragma unroll
            for (int ni = 0; ni < 4; ni++) {
                int cl = wcol + ni * 8 + lid * 2;
                atomicAdd(&scol[cl],     cs[ni][0]);
                atomicAdd(&scol[cl + 1], cs[ni][1]);
            }
        }
    }
    __syncthreads();
    if (tid < 128) {
        atomicAdd(&g_rowsum[row0 + tid], srow[tid]);
    } else if (!diag) {
        atomicAdd(&g_rowsum[col0 + tid - 128], scol[tid - 128]);
    }
}

// ---------------------------------------------------------------------------
// Kernel 3: final reduction -> mean loss.
// ---------------------------------------------------------------------------
__global__ void __launch_bounds__(1024) finalize_kernel(float* __restrict__ out) {
    float acc = 0.f;
    for (int r = threadIdx.x; r < NROWS; r += 1024)
        acc += 2.f + logf(g_rowsum[r]) - 2.f * g_tdot[r];
    #pragma unroll
    for (int o = 16; o > 0; o >>= 1) acc += __shfl_xor_sync(0xFFFFFFFF, acc, o);
    __shared__ float sh[32];
    int w = threadIdx.x >> 5, l = threadIdx.x & 31;
    if (l == 0) sh[w] = acc;
    __syncthreads();
    if (w == 0) {
        float v = sh[l];
        #pragma unroll
        for (int o = 16; o > 0; o >>= 1) v += __shfl_xor_sync(0xFFFFFFFF, v, o);
        if (l == 0) out[0] = v / (float)NROWS;
    }
}

// ---------------------------------------------------------------------------
extern "C" void kernel_launch(void* const* d_in, const int* in_sizes, int n_in,
                              void* d_out, int out_size) {
    const float* zis = (const float*)d_in[0];
    const float* zjs = (const float*)d_in[1];
    float* out = (float*)d_out;

    cudaFuncSetAttribute(gemm_kernel,
                         cudaFuncAttributeMaxDynamicSharedMemorySize, SMEM_TOTAL);

    normalize_kernel<<<NROWS / 8, 256>>>(zis, zjs);
    dim3 grid(65, 32);
    gemm_kernel<<<grid, 256, SMEM_TOTAL>>>();
    finalize_kernel<<<1, 1024>>>(out);
}

// round 6
// speedup vs baseline: 34.7990x; 1.3486x over previous
#include <cuda_runtime.h>
#include <cuda_bf16.h>
#include <math.h>
#include <stdint.h>

// NT-Xent loss. N=8192 rows (interleaved zjs/zis), D=256.
// score = 2*cos(i,j) in [-2,2] -> fixed-shift logsumexp:
//   loss_i = 2 + ln(sum_{j!=i} exp(2 d_ij - 2)) - 2 d_{i, i^1}
// Symmetric int8 IMMA GEMM with per-row quantization scales; exact
// triangular grid (2080 CTAs); dequant + shifted-exp fused epilogue.

#define NROWS 8192
#define DIM   256

__device__ __align__(16) int8_t g_q[NROWS * DIM];   // 2 MB quantized rows
__device__ float g_sc[NROWS];                       // per-row dequant scale
__device__ float g_rowsum[NROWS];
__device__ float g_tdot[NROWS];

// ---------------- helpers ----------------
__device__ __forceinline__ uint32_t smem_u32(const void* p) {
    uint32_t a;
    asm("{ .reg .u64 t; cvta.to.shared.u64 t, %1; cvt.u32.u64 %0, t; }"
        : "=r"(a) : "l"(p));
    return a;
}
__device__ __forceinline__ void cp16(uint32_t dst, const void* src) {
    asm volatile("cp.async.cg.shared.global [%0], [%1], 16;"
                 :: "r"(dst), "l"(src) : "memory");
}
__device__ __forceinline__ void ldsm_x4(uint32_t* r, uint32_t addr) {
    asm volatile("ldmatrix.sync.aligned.m8n8.x4.shared.b16 {%0,%1,%2,%3}, [%4];"
                 : "=r"(r[0]), "=r"(r[1]), "=r"(r[2]), "=r"(r[3]) : "r"(addr));
}
__device__ __forceinline__ void imma16832(int* c, const uint32_t* a,
                                          uint32_t b0, uint32_t b1) {
    asm volatile("mma.sync.aligned.m16n8k32.row.col.s32.s8.s8.s32 "
                 "{%0,%1,%2,%3}, {%4,%5,%6,%7}, {%8,%9}, {%0,%1,%2,%3};"
                 : "+r"(c[0]), "+r"(c[1]), "+r"(c[2]), "+r"(c[3])
                 : "r"(a[0]), "r"(a[1]), "r"(a[2]), "r"(a[3]), "r"(b0), "r"(b1));
}
__device__ __forceinline__ float fexp2(float x) {
    float e; asm("ex2.approx.ftz.f32 %0, %1;" : "=f"(e) : "f"(x)); return e;
}
__device__ __forceinline__ int qclamp(float x) {
    return __float2int_rn(x);   // |x| <= 127 by construction
}

// ---------------------------------------------------------------------------
// Kernel 1: interleave + fp32 normalize + per-row int8 quantize.
// One warp per row. Also zeroes g_rowsum.
// ---------------------------------------------------------------------------
__global__ void __launch_bounds__(256) normalize_kernel(
    const float* __restrict__ zis, const float* __restrict__ zjs) {
    int gtid = blockIdx.x * 256 + threadIdx.x;
    if (gtid < NROWS) g_rowsum[gtid] = 0.f;

    int w = threadIdx.x >> 5, lid = threadIdx.x & 31;
    int row = blockIdx.x * 8 + w;
    const float* src = (row & 1) ? (zis + (size_t)(row >> 1) * DIM)
                                 : (zjs + (size_t)(row >> 1) * DIM);
    float4 v0 = *reinterpret_cast<const float4*>(src + lid * 4);
    float4 v1 = *reinterpret_cast<const float4*>(src + 128 + lid * 4);
    float s = v0.x*v0.x + v0.y*v0.y + v0.z*v0.z + v0.w*v0.w
            + v1.x*v1.x + v1.y*v1.y + v1.z*v1.z + v1.w*v1.w;
    float mx = fmaxf(fmaxf(fmaxf(fabsf(v0.x), fabsf(v0.y)),
                           fmaxf(fabsf(v0.z), fabsf(v0.w))),
                     fmaxf(fmaxf(fabsf(v1.x), fabsf(v1.y)),
                           fmaxf(fabsf(v1.z), fabsf(v1.w))));
    #pragma unroll
    for (int o = 16; o > 0; o >>= 1) {
        s  += __shfl_xor_sync(0xFFFFFFFF, s, o);
        mx  = fmaxf(mx, __shfl_xor_sync(0xFFFFFFFF, mx, o));
    }
    float inv = 1.0f / fmaxf(sqrtf(s), 1e-8f);
    float mxn = fmaxf(mx * inv, 1e-20f);      // max |normalized element|
    float qmul = 127.0f / mxn;
    if (lid == 0) g_sc[row] = mxn * (1.0f / 127.0f);

    float k = inv * qmul;
    int q0 = qclamp(v0.x * k), q1 = qclamp(v0.y * k);
    int q2 = qclamp(v0.z * k), q3 = qclamp(v0.w * k);
    int q4 = qclamp(v1.x * k), q5 = qclamp(v1.y * k);
    int q6 = qclamp(v1.z * k), q7 = qclamp(v1.w * k);
    uint32_t w0 = (q0 & 0xff) | ((q1 & 0xff) << 8)
                | ((q2 & 0xff) << 16) | ((q3 & 0xff) << 24);
    uint32_t w1 = (q4 & 0xff) | ((q5 & 0xff) << 8)
                | ((q6 & 0xff) << 16) | ((q7 & 0xff) << 24);
    uint32_t* dst = reinterpret_cast<uint32_t*>(g_q + (size_t)row * DIM);
    dst[lid]      = w0;
    dst[32 + lid] = w1;
}

// ---------------------------------------------------------------------------
// Kernel 2: upper-triangle 128x128 int8 IMMA tiles + symmetric epilogue.
// grid (65, 32) packs the 2080-tile triangle exactly.
// 8 warps (2m x 4n), warp tile 64x32. 2-stage smem (64 KB) + scales (1 KB).
// ---------------------------------------------------------------------------
#define SM_SCALES 65536u
#define SMEM_TOTAL 66560

__global__ void __launch_bounds__(256, 2) gemm_kernel() {
    // triangular decode: pair row y (len 64-y) with row 63-y (len y+1)
    const int x = blockIdx.x, y = blockIdx.y;
    int by, bx;
    if (x < 64 - y) { by = y;      bx = y + x; }
    else            { by = 63 - y; bx = x - 1; }
    const bool diag = (bx == by);

    extern __shared__ __align__(16) char smem[];
    const uint32_t sb = smem_u32(smem);
    const int tid = threadIdx.x;
    const int lid = tid & 31;
    const int wid = tid >> 5;
    const int wm = wid >> 2;
    const int wn = wid & 3;
    const int wrow = wm * 64;
    const int wcol = wn * 32;
    const int row0 = by * 128;
    const int col0 = bx * 128;

    int c[4][4][4];
    #pragma unroll
    for (int mi = 0; mi < 4; mi++)
        #pragma unroll
        for (int ni = 0; ni < 4; ni++)
            #pragma unroll
            for (int q = 0; q < 4; q++) c[mi][ni][q] = 0;

    const char* gA = (const char*)g_q + (size_t)row0 * 256;
    const char* gB = (const char*)g_q + (size_t)col0 * 256;

    // scales into smem (row[128] then col[128] floats)
    if (tid < 128) {
        ((float*)(smem + SM_SCALES))[tid]       = g_sc[row0 + tid];
        ((float*)(smem + SM_SCALES))[128 + tid] = g_sc[col0 + tid];
    }

    // ---- stage loader: K-half ch (128 B of each row) into stage s (32 KB) ----
    auto load_stage = [&](int ch, int s) {
        uint32_t dA = sb + (uint32_t)s * 32768u;
        const char* srcA = gA + ch * 128;
        #pragma unroll
        for (int it = 0; it < 4; it++) {
            int i = it * 256 + tid;          // 0..1023
            int r = i >> 3, g = i & 7;
            uint32_t off = (uint32_t)(r * 128 + ((g * 16) ^ ((r & 7) << 4)));
            cp16(dA + off, srcA + (size_t)r * 256 + g * 16);
        }
        if (!diag) {
            uint32_t dB = dA + 16384u;
            const char* srcB = gB + ch * 128;
            #pragma unroll
            for (int it = 0; it < 4; it++) {
                int i = it * 256 + tid;
                int r = i >> 3, g = i & 7;
                uint32_t off = (uint32_t)(r * 128 + ((g * 16) ^ ((r & 7) << 4)));
                cp16(dB + off, srcB + (size_t)r * 256 + g * 16);
            }
        }
        asm volatile("cp.async.commit_group;" ::: "memory");
    };

    const int lg = lid & 7;
    const int ltile = lid >> 3;
    const int trow8 = (ltile & 1) * 8;
    const int tk16 = (ltile >> 1) * 16;

    auto compute = [&](int s) {
        uint32_t asb = sb + (uint32_t)s * 32768u;
        uint32_t bsb = diag ? asb : (asb + 16384u);
        #pragma unroll
        for (int k32 = 0; k32 < 4; k32++) {
            int kb = k32 * 32 + tk16;
            uint32_t a[4][4], bb[2][4];
            #pragma unroll
            for (int mi = 0; mi < 4; mi++) {
                int m = wrow + mi * 16 + trow8 + lg;
                ldsm_x4(a[mi], asb + (uint32_t)(m * 128 + (kb ^ ((m & 7) << 4))));
            }
            #pragma unroll
            for (int nb = 0; nb < 2; nb++) {
                int n = wcol + nb * 16 + trow8 + lg;
                ldsm_x4(bb[nb], bsb + (uint32_t)(n * 128 + (kb ^ ((n & 7) << 4))));
            }
            #pragma unroll
            for (int mi = 0; mi < 4; mi++) {
                #pragma unroll
                for (int ni = 0; ni < 4; ni++) {
                    const uint32_t* B = bb[ni >> 1];
                    uint32_t b0 = (ni & 1) ? B[1] : B[0];
                    uint32_t b1 = (ni & 1) ? B[3] : B[2];
                    imma16832(c[mi][ni], a[mi], b0, b1);
                }
            }
        }
    };

    // ---- two K-halves, 2-stage pipeline ----
    load_stage(0, 0);
    load_stage(1, 1);
    asm volatile("cp.async.wait_group 1;" ::: "memory");
    __syncthreads();
    compute(0);
    asm volatile("cp.async.wait_group 0;" ::: "memory");
    __syncthreads();
    compute(1);
    __syncthreads();

    // ---- epilogue: dequant + shifted exp-sum ----
    const float C1 = 2.885390081777927f;   // 2*log2(e)
    const float* rsc = (const float*)(smem + SM_SCALES);
    const float* csc = rsc + 128;
    float* srow = (float*)smem;            // [128] row exp-sums
    float* scol = srow + 128;              // [128] col exp-sums
    if (tid < 256) srow[tid] = 0.f;
    __syncthreads();

    float rs[4][2], cs[4][2];
    #pragma unroll
    for (int i = 0; i < 4; i++) { rs[i][0]=rs[i][1]=0.f; cs[i][0]=cs[i][1]=0.f; }

    #pragma unroll
    for (int mi = 0; mi < 4; mi++) {
        int rl0 = wrow + mi * 16 + (lid >> 2);
        int rl1 = rl0 + 8;
        int r0 = row0 + rl0, r1 = row0 + rl1;
        float s0 = rsc[rl0], s1 = rsc[rl1];
        #pragma unroll
        for (int ni = 0; ni < 4; ni++) {
            int cl = wcol + ni * 8 + (lid & 3) * 2;
            int cb = col0 + cl;
            float sc0 = csc[cl], sc1 = csc[cl + 1];
            float d0 = (float)c[mi][ni][0] * (s0 * sc0);
            float d1 = (float)c[mi][ni][1] * (s0 * sc1);
            float d2 = (float)c[mi][ni][2] * (s1 * sc0);
            float d3 = (float)c[mi][ni][3] * (s1 * sc1);
            float e0 = fexp2(fmaf(d0, C1, -C1));
            float e1 = fexp2(fmaf(d1, C1, -C1));
            float e2 = fexp2(fmaf(d2, C1, -C1));
            float e3 = fexp2(fmaf(d3, C1, -C1));
            if (diag) {
                if (cb     == r0) e0 = 0.f;
                if (cb + 1 == r0) e1 = 0.f;
                if (cb     == r1) e2 = 0.f;
                if (cb + 1 == r1) e3 = 0.f;
                if (cb     == (r0 ^ 1)) g_tdot[r0] = d0;
                if (cb + 1 == (r0 ^ 1)) g_tdot[r0] = d1;
                if (cb     == (r1 ^ 1)) g_tdot[r1] = d2;
                if (cb + 1 == (r1 ^ 1)) g_tdot[r1] = d3;
            }
            rs[mi][0] += e0 + e1;
            rs[mi][1] += e2 + e3;
            cs[ni][0] += e0 + e2;
            cs[ni][1] += e1 + e3;
        }
    }

    // rows: reduce across the 4 lanes sharing each row
    #pragma unroll
    for (int mi = 0; mi < 4; mi++) {
        #pragma unroll
        for (int h = 0; h < 2; h++) {
            rs[mi][h] += __shfl_xor_sync(0xFFFFFFFF, rs[mi][h], 1);
            rs[mi][h] += __shfl_xor_sync(0xFFFFFFFF, rs[mi][h], 2);
        }
    }
    if ((lid & 3) == 0) {
        int rl = wrow + (lid >> 2);
        #pragma unroll
        for (int mi = 0; mi < 4; mi++) {
            atomicAdd(&srow[rl + mi * 16],     rs[mi][0]);
            atomicAdd(&srow[rl + mi * 16 + 8], rs[mi][1]);
        }
    }
    // cols (offdiag only): reduce across the 8 lanes sharing each column pair
    if (!diag) {
        #pragma unroll
        for (int ni = 0; ni < 4; ni++) {
            #pragma unroll
            for (int h = 0; h < 2; h++) {
                cs[ni][h] += __shfl_xor_sync(0xFFFFFFFF, cs[ni][h], 4);
                cs[ni][h] += __shfl_xor_sync(0xFFFFFFFF, cs[ni][h], 8);
                cs[ni][h] += __shfl_xor_sync(0xFFFFFFFF, cs[ni][h], 16);
            }
        }
        if (lid < 4) {
            #pragma unroll
            for (int ni = 0; ni < 4; ni++) {
                int cl = wcol + ni * 8 + lid * 2;
                atomicAdd(&scol[cl],     cs[ni][0]);
                atomicAdd(&scol[cl + 1], cs[ni][1]);
            }
        }
    }
    __syncthreads();
    if (tid < 128) {
        atomicAdd(&g_rowsum[row0 + tid], srow[tid]);
    } else if (!diag) {
        atomicAdd(&g_rowsum[col0 + tid - 128], scol[tid - 128]);
    }
}

// ---------------------------------------------------------------------------
// Kernel 3: final reduction -> mean loss.
// ---------------------------------------------------------------------------
__global__ void __launch_bounds__(1024) finalize_kernel(float* __restrict__ out) {
    float acc = 0.f;
    for (int r = threadIdx.x; r < NROWS; r += 1024)
        acc += 2.f + logf(g_rowsum[r]) - 2.f * g_tdot[r];
    #pragma unroll
    for (int o = 16; o > 0; o >>= 1) acc += __shfl_xor_sync(0xFFFFFFFF, acc, o);
    __shared__ float sh[32];
    int w = threadIdx.x >> 5, l = threadIdx.x & 31;
    if (l == 0) sh[w] = acc;
    __syncthreads();
    if (w == 0) {
        float v = sh[l];
        #pragma unroll
        for (int o = 16; o > 0; o >>= 1) v += __shfl_xor_sync(0xFFFFFFFF, v, o);
        if (l == 0) out[0] = v / (float)NROWS;
    }
}

// ---------------------------------------------------------------------------
extern "C" void kernel_launch(void* const* d_in, const int* in_sizes, int n_in,
                              void* d_out, int out_size) {
    const float* zis = (const float*)d_in[0];
    const float* zjs = (const float*)d_in[1];
    float* out = (float*)d_out;

    cudaFuncSetAttribute(gemm_kernel,
                         cudaFuncAttributeMaxDynamicSharedMemorySize, SMEM_TOTAL);

    normalize_kernel<<<NROWS / 8, 256>>>(zis, zjs);
    dim3 grid(65, 32);
    gemm_kernel<<<grid, 256, SMEM_TOTAL>>>();
    finalize_kernel<<<1, 1024>>>(out);
}